// round 1
// baseline (speedup 1.0000x reference)
#include <cuda_runtime.h>
#include <math.h>

#define N_NODES 100000
#define N_EDGES 1000000
#define IN_DIM  128
#define HID     64
#define NET     4
#define G_GRAPHS 128
#define LBL     10
#define N_STEPS 5

// ---------------- scratch (static device globals; no allocation) ----------------
static __device__ float g_h[(size_t)N_NODES * HID];              // 25.6 MB
static __device__ float g_trans[(size_t)N_NODES * NET * HID];    // 102.4 MB, layout [N][NET*HID]
static __device__ float g_a[(size_t)N_NODES * HID];              // 25.6 MB
static __device__ float g_gi[(size_t)N_NODES * 3 * HID];         // 76.8 MB
static __device__ float g_gh[(size_t)N_NODES * 3 * HID];         // 76.8 MB
static __device__ float g_hg[G_GRAPHS * HID];
static __device__ float g_cnt[G_GRAPHS];

// ---------------- generic fp32 GEMM: C[M,NCOLS] = A[M,K] @ W[NCOLS,K]^T + bias ----------------
// BM=64, BN=64, BK=16, 256 threads, 4x4 microtile per thread.
template<int K, int NCOLS>
__global__ void __launch_bounds__(256) gemm_bias(
    const float* __restrict__ A, const float* __restrict__ W,
    const float* __restrict__ bias, float* __restrict__ C, int M)
{
    constexpr int BM = 64, BN = 64, BK = 16;
    __shared__ __align__(16) float As[BK][BM];
    __shared__ __align__(16) float Bs[BK][BN];

    const int row0 = blockIdx.x * BM;
    const int col0 = blockIdx.y * BN;
    const int tid  = threadIdx.x;
    const int tx   = tid & 15;     // 0..15  -> output col group
    const int ty   = tid >> 4;     // 0..15  -> output row group
    const int lr   = tid >> 2;     // 0..63  loader row/col within tile
    const int lk   = (tid & 3) * 4;// k offset 0,4,8,12

    int arow = row0 + lr; if (arow >= M) arow = M - 1;   // clamp; stores are guarded
    const int brow = col0 + lr;                          // NCOLS % 64 == 0, always valid

    float acc[4][4];
#pragma unroll
    for (int i = 0; i < 4; i++)
#pragma unroll
        for (int j = 0; j < 4; j++) acc[i][j] = 0.f;

    for (int k0 = 0; k0 < K; k0 += BK) {
        float4 av = *(const float4*)(A + (size_t)arow * K + k0 + lk);
        float4 bv = *(const float4*)(W + (size_t)brow * K + k0 + lk);
        As[lk + 0][lr] = av.x; As[lk + 1][lr] = av.y;
        As[lk + 2][lr] = av.z; As[lk + 3][lr] = av.w;
        Bs[lk + 0][lr] = bv.x; Bs[lk + 1][lr] = bv.y;
        Bs[lk + 2][lr] = bv.z; Bs[lk + 3][lr] = bv.w;
        __syncthreads();
#pragma unroll
        for (int kk = 0; kk < BK; kk++) {
            float4 a4 = *(const float4*)&As[kk][ty * 4];
            float4 b4 = *(const float4*)&Bs[kk][tx * 4];
            float aa[4] = {a4.x, a4.y, a4.z, a4.w};
            float bb[4] = {b4.x, b4.y, b4.z, b4.w};
#pragma unroll
            for (int i = 0; i < 4; i++)
#pragma unroll
                for (int j = 0; j < 4; j++)
                    acc[i][j] += aa[i] * bb[j];
        }
        __syncthreads();
    }

    float4 bias4 = *(const float4*)(bias + col0 + tx * 4);
    float bb[4] = {bias4.x, bias4.y, bias4.z, bias4.w};
#pragma unroll
    for (int i = 0; i < 4; i++) {
        int r = row0 + ty * 4 + i;
        if (r < M) {
            float4 o = make_float4(acc[i][0] + bb[0], acc[i][1] + bb[1],
                                   acc[i][2] + bb[2], acc[i][3] + bb[3]);
            *(float4*)(C + (size_t)r * NCOLS + col0 + tx * 4) = o;
        }
    }
}

// ---------------- zero helpers ----------------
__global__ void zero_a() {
    size_t t = (size_t)blockIdx.x * blockDim.x + threadIdx.x;
    size_t n4 = (size_t)N_NODES * HID / 4;
    if (t < n4) ((float4*)g_a)[t] = make_float4(0.f, 0.f, 0.f, 0.f);
}
__global__ void zero_pool() {
    int t = threadIdx.x;
    for (int i = t; i < G_GRAPHS * HID; i += blockDim.x) g_hg[i] = 0.f;
    if (t < G_GRAPHS) g_cnt[t] = 0.f;
}

// ---------------- edge gather + scatter-add: a[dst] += trans[src][etype] ----------------
// 16 threads per edge, each moves one float4 with a vector reduction.
__global__ void edge_scatter(const int* __restrict__ src, const int* __restrict__ dst,
                             const int* __restrict__ et)
{
    long long t = (long long)blockIdx.x * blockDim.x + threadIdx.x;
    int e = (int)(t >> 4);
    if (e >= N_EDGES) return;
    int q = (int)(t & 15) << 2;
    int s  = __ldg(src + e);
    int d  = __ldg(dst + e);
    int ty = __ldg(et  + e);
    const float4 v = *(const float4*)&g_trans[((size_t)s * NET + ty) * HID + q];
    float* out = &g_a[(size_t)d * HID + q];
    asm volatile("red.global.add.v4.f32 [%0], {%1,%2,%3,%4};"
                 :: "l"(out), "f"(v.x), "f"(v.y), "f"(v.z), "f"(v.w) : "memory");
}

// ---------------- GRU elementwise update (in place on g_h) ----------------
__global__ void gru_update(int M) {
    long long t = (long long)blockIdx.x * blockDim.x + threadIdx.x;
    if (t >= (long long)M * HID) return;
    int n = (int)(t >> 6), j = (int)(t & 63);
    const float* gi = g_gi + (size_t)n * 3 * HID;
    const float* gh = g_gh + (size_t)n * 3 * HID;
    float r  = 1.f / (1.f + __expf(-(gi[j]        + gh[j])));
    float z  = 1.f / (1.f + __expf(-(gi[HID + j]  + gh[HID + j])));
    float nn = tanhf(gi[2 * HID + j] + r * gh[2 * HID + j]);
    float h  = g_h[t];
    g_h[t] = (1.f - z) * nn + z * h;
}

// ---------------- per-graph mean pool (node2graph is sorted -> segment accumulate) ----------------
__global__ void pool_kernel(const int* __restrict__ n2g) {
    constexpr int CHUNK = 256;
    int j = threadIdx.x;                 // 64 threads, one per hidden dim
    int start = blockIdx.x * CHUNK;
    int end   = min(start + CHUNK, N_NODES);
    if (start >= end) return;
    float sum = 0.f, c = 0.f;
    int g = __ldg(n2g + start);
    for (int n = start; n < end; n++) {
        int gn = __ldg(n2g + n);
        if (gn != g) {
            atomicAdd(&g_hg[g * HID + j], sum);
            if (j == 0) atomicAdd(&g_cnt[g], c);
            sum = 0.f; c = 0.f; g = gn;
        }
        sum += g_h[(size_t)n * HID + j];
        c += 1.f;
    }
    atomicAdd(&g_hg[g * HID + j], sum);
    if (j == 0) atomicAdd(&g_cnt[g], c);
}

// ---------------- classifier: out = relu(hg@W1^T + b1)@W2^T + b2 ----------------
__global__ void classifier_kernel(const float* __restrict__ W1, const float* __restrict__ b1,
                                  const float* __restrict__ W2, const float* __restrict__ b2,
                                  float* __restrict__ out)
{
    __shared__ float sW1[32 * 64];
    __shared__ float sW2[10 * 32];
    __shared__ float sHG[G_GRAPHS][HID + 1];   // +1 pad: conflict-free column reads
    int t = threadIdx.x;                       // 128 threads
    for (int i = t; i < 32 * 64; i += 128) sW1[i] = W1[i];
    for (int i = t; i < 10 * 32; i += 128) sW2[i] = W2[i];
    for (int i = t; i < G_GRAPHS * HID; i += 128) {
        int g = i >> 6;
        sHG[g][i & 63] = g_hg[i] / fmaxf(g_cnt[g], 1.f);
    }
    __syncthreads();
    int g = t;  // one graph per thread
    float mid[32];
#pragma unroll
    for (int m = 0; m < 32; m++) {
        float s = b1[m];
#pragma unroll
        for (int k = 0; k < 64; k++) s += sHG[g][k] * sW1[m * 64 + k];
        mid[m] = fmaxf(s, 0.f);
    }
#pragma unroll
    for (int l = 0; l < LBL; l++) {
        float s = b2[l];
#pragma unroll
        for (int k = 0; k < 32; k++) s += mid[k] * sW2[l * 32 + k];
        out[g * LBL + l] = s;
    }
}

// ---------------- launch ----------------
extern "C" void kernel_launch(void* const* d_in, const int* in_sizes, int n_in,
                              void* d_out, int out_size)
{
    const float* x    = (const float*)d_in[0];
    const int*   src  = (const int*)d_in[1];
    const int*   dst  = (const int*)d_in[2];
    const int*   et   = (const int*)d_in[3];
    const int*   n2g  = (const int*)d_in[4];
    const float* W_in = (const float*)d_in[5];
    const float* b_in = (const float*)d_in[6];
    const float* We   = (const float*)d_in[7];   // [NET*HID][HID] contiguous
    const float* be   = (const float*)d_in[8];   // [NET*HID]
    const float* W_ih = (const float*)d_in[9];
    const float* b_ih = (const float*)d_in[10];
    const float* W_hh = (const float*)d_in[11];
    const float* b_hh = (const float*)d_in[12];
    const float* W1   = (const float*)d_in[13];
    const float* b1   = (const float*)d_in[14];
    const float* W2   = (const float*)d_in[15];
    const float* b2   = (const float*)d_in[16];
    float* out = (float*)d_out;

    void *p;
    cudaGetSymbolAddress(&p, g_h);     float* ph  = (float*)p;
    cudaGetSymbolAddress(&p, g_trans); float* ptr = (float*)p;
    cudaGetSymbolAddress(&p, g_a);     float* pa  = (float*)p;
    cudaGetSymbolAddress(&p, g_gi);    float* pgi = (float*)p;
    cudaGetSymbolAddress(&p, g_gh);    float* pgh = (float*)p;

    const int M = N_NODES;
    const int gx = (M + 63) / 64;

    // h = x @ W_in^T + b_in
    gemm_bias<IN_DIM, HID><<<dim3(gx, 1), 256>>>(x, W_in, b_in, ph, M);

    for (int s = 0; s < N_STEPS; s++) {
        // trans[n][e*64+j] = h @ We^T + be  (all 4 etypes as one 256-wide GEMM)
        gemm_bias<HID, NET * HID><<<dim3(gx, NET), 256>>>(ph, We, be, ptr, M);
        // a = segment_sum over edges
        zero_a<<<((N_NODES * HID / 4) + 255) / 256, 256>>>();
        edge_scatter<<<(int)(((long long)N_EDGES * 16 + 255) / 256), 256>>>(src, dst, et);
        // GRU gates
        gemm_bias<HID, 3 * HID><<<dim3(gx, 3), 256>>>(pa, W_ih, b_ih, pgi, M);
        gemm_bias<HID, 3 * HID><<<dim3(gx, 3), 256>>>(ph, W_hh, b_hh, pgh, M);
        gru_update<<<(int)(((long long)M * HID + 255) / 256), 256>>>(M);
    }

    // mean pool + classifier
    zero_pool<<<1, 256>>>();
    pool_kernel<<<(M + 255) / 256, 64>>>(n2g);
    classifier_kernel<<<1, 128>>>(W1, b1, W2, b2, out);
}

// round 2
// speedup vs baseline: 1.1498x; 1.1498x over previous
#include <cuda_runtime.h>
#include <math.h>

#define N_NODES 100000
#define N_EDGES 1000000
#define IN_DIM  128
#define HID     64
#define NET     4
#define G_GRAPHS 128
#define LBL     10
#define N_STEPS 5

// ---------------- scratch ----------------
static __device__ float g_h[(size_t)N_NODES * HID];
static __device__ float g_trans[(size_t)N_NODES * NET * HID];
static __device__ float g_a[(size_t)N_NODES * HID];
static __device__ float g_hg[G_GRAPHS * HID];
static __device__ float g_cnt[G_GRAPHS];

// ---------------- GEMM: C[M,NCOLS] = A[M,K] @ W[NCOLS,K]^T + bias ----------------
// BM=128, BN=64, BK=16, 128 threads, 8x8 microtile. 64 FMA / 64B LDS per thread-kk.
template<int K, int NCOLS>
__global__ void __launch_bounds__(128) gemm_bias2(
    const float* __restrict__ A, const float* __restrict__ W,
    const float* __restrict__ bias, float* __restrict__ C, int M)
{
    constexpr int BM = 128, BN = 64, BK = 16;
    __shared__ __align__(16) float As[BK][BM];
    __shared__ __align__(16) float Bs[BK][BN];

    const int row0 = blockIdx.x * BM;
    const int col0 = blockIdx.y * BN;
    const int tid  = threadIdx.x;
    const int tx   = tid & 7;     // 8 col groups of 8
    const int ty   = tid >> 3;    // 16 row groups of 8

    float acc[8][8];
#pragma unroll
    for (int i = 0; i < 8; i++)
#pragma unroll
        for (int j = 0; j < 8; j++) acc[i][j] = 0.f;

    // A loader: one row per thread
    int arow = row0 + tid; if (arow >= M) arow = M - 1;
    const float* Arow = A + (size_t)arow * K;
    // B loader: threads 0..63 each own one row of the 64-row W tile
    const float* Wrow = W + (size_t)(col0 + (tid & 63)) * K;

    for (int k0 = 0; k0 < K; k0 += BK) {
#pragma unroll
        for (int u = 0; u < 4; u++) {
            float4 v = __ldg((const float4*)(Arow + k0 + u * 4));
            As[u * 4 + 0][tid] = v.x; As[u * 4 + 1][tid] = v.y;
            As[u * 4 + 2][tid] = v.z; As[u * 4 + 3][tid] = v.w;
        }
        if (tid < 64) {
#pragma unroll
            for (int u = 0; u < 4; u++) {
                float4 v = __ldg((const float4*)(Wrow + k0 + u * 4));
                Bs[u * 4 + 0][tid] = v.x; Bs[u * 4 + 1][tid] = v.y;
                Bs[u * 4 + 2][tid] = v.z; Bs[u * 4 + 3][tid] = v.w;
            }
        }
        __syncthreads();
#pragma unroll
        for (int kk = 0; kk < BK; kk++) {
            float a[8], b[8];
            *(float4*)&a[0] = *(const float4*)&As[kk][ty * 8];
            *(float4*)&a[4] = *(const float4*)&As[kk][ty * 8 + 4];
            *(float4*)&b[0] = *(const float4*)&Bs[kk][tx * 8];
            *(float4*)&b[4] = *(const float4*)&Bs[kk][tx * 8 + 4];
#pragma unroll
            for (int i = 0; i < 8; i++)
#pragma unroll
                for (int j = 0; j < 8; j++)
                    acc[i][j] += a[i] * b[j];
        }
        __syncthreads();
    }

    float bb[8];
    *(float4*)&bb[0] = __ldg((const float4*)(bias + col0 + tx * 8));
    *(float4*)&bb[4] = __ldg((const float4*)(bias + col0 + tx * 8 + 4));
#pragma unroll
    for (int i = 0; i < 8; i++) {
        int r = row0 + ty * 8 + i;
        if (r < M) {
            float4 o0 = make_float4(acc[i][0] + bb[0], acc[i][1] + bb[1],
                                    acc[i][2] + bb[2], acc[i][3] + bb[3]);
            float4 o1 = make_float4(acc[i][4] + bb[4], acc[i][5] + bb[5],
                                    acc[i][6] + bb[6], acc[i][7] + bb[7]);
            *(float4*)(C + (size_t)r * NCOLS + col0 + tx * 8) = o0;
            *(float4*)(C + (size_t)r * NCOLS + col0 + tx * 8 + 4) = o1;
        }
    }
}

// ---------------- fused GRU: gi = a@W_ih^T, gh = h@W_hh^T, gate math, h update ----------------
// BM=64 nodes per block, 256 threads, per-thread 4x4 patches of r/z/in/hn accumulators.
__global__ void __launch_bounds__(256) gru_fused(
    const float* __restrict__ Wih, const float* __restrict__ bih,
    const float* __restrict__ Whh, const float* __restrict__ bhh, int M)
{
    __shared__ __align__(16) float As[16][64];
    __shared__ __align__(16) float Ws[16][192];

    const int row0 = blockIdx.x * 64;
    const int tid  = threadIdx.x;
    const int tx   = tid & 15;    // col group (4 cols)
    const int ty   = tid >> 4;    // row group (4 rows)

    float accr[4][4], accz[4][4], accni[4][4], accnh[4][4];
#pragma unroll
    for (int i = 0; i < 4; i++)
#pragma unroll
        for (int j = 0; j < 4; j++) {
            accr[i][j] = 0.f; accz[i][j] = 0.f;
            accni[i][j] = 0.f; accnh[i][j] = 0.f;
        }

    int lrow = row0 + (tid >> 2); if (lrow >= M) lrow = M - 1;
    const int lk = (tid & 3) * 4;
    const int wrow = (tid < 192) ? tid : 191;   // weight loader: one row per thread (<192)

#pragma unroll
    for (int p = 0; p < 2; p++) {
        const float* Ap = p ? g_h : g_a;
        const float* Wp = p ? Whh : Wih;
        const float* Wr = Wp + (size_t)wrow * HID;
        for (int k0 = 0; k0 < 64; k0 += 16) {
            float4 v = __ldg((const float4*)(Ap + (size_t)lrow * HID + k0 + lk));
            As[lk + 0][tid >> 2] = v.x; As[lk + 1][tid >> 2] = v.y;
            As[lk + 2][tid >> 2] = v.z; As[lk + 3][tid >> 2] = v.w;
            if (tid < 192) {
#pragma unroll
                for (int u = 0; u < 4; u++) {
                    float4 w = __ldg((const float4*)(Wr + k0 + u * 4));
                    Ws[u * 4 + 0][wrow] = w.x; Ws[u * 4 + 1][wrow] = w.y;
                    Ws[u * 4 + 2][wrow] = w.z; Ws[u * 4 + 3][wrow] = w.w;
                }
            }
            __syncthreads();
#pragma unroll
            for (int kk = 0; kk < 16; kk++) {
                float4 a4 = *(const float4*)&As[kk][ty * 4];
                float4 r4 = *(const float4*)&Ws[kk][tx * 4];
                float4 z4 = *(const float4*)&Ws[kk][64 + tx * 4];
                float4 n4 = *(const float4*)&Ws[kk][128 + tx * 4];
                float a[4] = {a4.x, a4.y, a4.z, a4.w};
                float wr[4] = {r4.x, r4.y, r4.z, r4.w};
                float wz[4] = {z4.x, z4.y, z4.z, z4.w};
                float wn[4] = {n4.x, n4.y, n4.z, n4.w};
#pragma unroll
                for (int i = 0; i < 4; i++)
#pragma unroll
                    for (int j = 0; j < 4; j++) {
                        accr[i][j] += a[i] * wr[j];
                        accz[i][j] += a[i] * wz[j];
                        if (p == 0) accni[i][j] += a[i] * wn[j];
                        else        accnh[i][j] += a[i] * wn[j];
                    }
            }
            __syncthreads();
        }
    }

    // epilogue: GRU gate math, in-place h update (block owns its rows exclusively)
    const int c = tx * 4;
    float4 birv = __ldg((const float4*)(bih + c));
    float4 bhrv = __ldg((const float4*)(bhh + c));
    float4 bizv = __ldg((const float4*)(bih + 64 + c));
    float4 bhzv = __ldg((const float4*)(bhh + 64 + c));
    float4 binv = __ldg((const float4*)(bih + 128 + c));
    float4 bhnv = __ldg((const float4*)(bhh + 128 + c));
    float br[4] = {birv.x + bhrv.x, birv.y + bhrv.y, birv.z + bhrv.z, birv.w + bhrv.w};
    float bz[4] = {bizv.x + bhzv.x, bizv.y + bhzv.y, bizv.z + bhzv.z, bizv.w + bhzv.w};
    float bi[4] = {binv.x, binv.y, binv.z, binv.w};
    float bh[4] = {bhnv.x, bhnv.y, bhnv.z, bhnv.w};

#pragma unroll
    for (int i = 0; i < 4; i++) {
        int r = row0 + ty * 4 + i;
        if (r < M) {
            float* hp = &g_h[(size_t)r * HID + c];
            float4 hold = *(const float4*)hp;
            float ho[4] = {hold.x, hold.y, hold.z, hold.w};
            float out[4];
#pragma unroll
            for (int j = 0; j < 4; j++) {
                float rr = 1.f / (1.f + __expf(-(accr[i][j] + br[j])));
                float zz = 1.f / (1.f + __expf(-(accz[i][j] + bz[j])));
                float nn = tanhf(accni[i][j] + bi[j] + rr * (accnh[i][j] + bh[j]));
                out[j] = (1.f - zz) * nn + zz * ho[j];
            }
            *(float4*)hp = make_float4(out[0], out[1], out[2], out[3]);
        }
    }
}

// ---------------- zero helpers ----------------
__global__ void zero_a() {
    size_t t = (size_t)blockIdx.x * blockDim.x + threadIdx.x;
    size_t n4 = (size_t)N_NODES * HID / 4;
    if (t < n4) ((float4*)g_a)[t] = make_float4(0.f, 0.f, 0.f, 0.f);
}
__global__ void zero_pool() {
    int t = threadIdx.x;
    for (int i = t; i < G_GRAPHS * HID; i += blockDim.x) g_hg[i] = 0.f;
    if (t < G_GRAPHS) g_cnt[t] = 0.f;
}

// ---------------- edge scatter: a[dst] += trans[src][etype] ----------------
__global__ void edge_scatter(const int* __restrict__ src, const int* __restrict__ dst,
                             const int* __restrict__ et)
{
    long long t = (long long)blockIdx.x * blockDim.x + threadIdx.x;
    int e = (int)(t >> 4);
    if (e >= N_EDGES) return;
    int q = (int)(t & 15) << 2;
    int s  = __ldg(src + e);
    int d  = __ldg(dst + e);
    int ty = __ldg(et  + e);
    float4 v = __ldg((const float4*)&g_trans[((size_t)s * NET + ty) * HID + q]);
    float* out = &g_a[(size_t)d * HID + q];
    asm volatile("red.global.add.v4.f32 [%0], {%1,%2,%3,%4};"
                 :: "l"(out), "f"(v.x), "f"(v.y), "f"(v.z), "f"(v.w) : "memory");
}

// ---------------- per-graph mean pool ----------------
__global__ void pool_kernel(const int* __restrict__ n2g) {
    constexpr int CHUNK = 256;
    int j = threadIdx.x;
    int start = blockIdx.x * CHUNK;
    int end   = min(start + CHUNK, N_NODES);
    if (start >= end) return;
    float sum = 0.f, c = 0.f;
    int g = __ldg(n2g + start);
    for (int n = start; n < end; n++) {
        int gn = __ldg(n2g + n);
        if (gn != g) {
            atomicAdd(&g_hg[g * HID + j], sum);
            if (j == 0) atomicAdd(&g_cnt[g], c);
            sum = 0.f; c = 0.f; g = gn;
        }
        sum += g_h[(size_t)n * HID + j];
        c += 1.f;
    }
    atomicAdd(&g_hg[g * HID + j], sum);
    if (j == 0) atomicAdd(&g_cnt[g], c);
}

// ---------------- classifier ----------------
__global__ void classifier_kernel(const float* __restrict__ W1, const float* __restrict__ b1,
                                  const float* __restrict__ W2, const float* __restrict__ b2,
                                  float* __restrict__ out)
{
    __shared__ float sW1[32 * 64];
    __shared__ float sW2[10 * 32];
    __shared__ float sHG[G_GRAPHS][HID + 1];
    int t = threadIdx.x;
    for (int i = t; i < 32 * 64; i += 128) sW1[i] = W1[i];
    for (int i = t; i < 10 * 32; i += 128) sW2[i] = W2[i];
    for (int i = t; i < G_GRAPHS * HID; i += 128) {
        int g = i >> 6;
        sHG[g][i & 63] = g_hg[i] / fmaxf(g_cnt[g], 1.f);
    }
    __syncthreads();
    int g = t;
    float mid[32];
#pragma unroll
    for (int m = 0; m < 32; m++) {
        float s = b1[m];
#pragma unroll
        for (int k = 0; k < 64; k++) s += sHG[g][k] * sW1[m * 64 + k];
        mid[m] = fmaxf(s, 0.f);
    }
#pragma unroll
    for (int l = 0; l < LBL; l++) {
        float s = b2[l];
#pragma unroll
        for (int k = 0; k < 32; k++) s += mid[k] * sW2[l * 32 + k];
        out[g * LBL + l] = s;
    }
}

// ---------------- launch ----------------
extern "C" void kernel_launch(void* const* d_in, const int* in_sizes, int n_in,
                              void* d_out, int out_size)
{
    const float* x    = (const float*)d_in[0];
    const int*   src  = (const int*)d_in[1];
    const int*   dst  = (const int*)d_in[2];
    const int*   et   = (const int*)d_in[3];
    const int*   n2g  = (const int*)d_in[4];
    const float* W_in = (const float*)d_in[5];
    const float* b_in = (const float*)d_in[6];
    const float* We   = (const float*)d_in[7];
    const float* be   = (const float*)d_in[8];
    const float* W_ih = (const float*)d_in[9];
    const float* b_ih = (const float*)d_in[10];
    const float* W_hh = (const float*)d_in[11];
    const float* b_hh = (const float*)d_in[12];
    const float* W1   = (const float*)d_in[13];
    const float* b1   = (const float*)d_in[14];
    const float* W2   = (const float*)d_in[15];
    const float* b2   = (const float*)d_in[16];
    float* out = (float*)d_out;

    void *p;
    cudaGetSymbolAddress(&p, g_h);     float* ph  = (float*)p;
    cudaGetSymbolAddress(&p, g_trans); float* ptr = (float*)p;

    const int M = N_NODES;
    const int gx128 = (M + 127) / 128;
    const int gx64  = (M + 63) / 64;

    // h = x @ W_in^T + b_in
    gemm_bias2<IN_DIM, HID><<<dim3(gx128, 1), 128>>>(x, W_in, b_in, ph, M);

    for (int s = 0; s < N_STEPS; s++) {
        gemm_bias2<HID, NET * HID><<<dim3(gx128, NET), 128>>>(ph, We, be, ptr, M);
        zero_a<<<((N_NODES * HID / 4) + 255) / 256, 256>>>();
        edge_scatter<<<(int)(((long long)N_EDGES * 16 + 255) / 256), 256>>>(src, dst, et);
        gru_fused<<<gx64, 256>>>(W_ih, b_ih, W_hh, b_hh, M);
    }

    zero_pool<<<1, 256>>>();
    pool_kernel<<<(M + 255) / 256, 64>>>(n2g);
    classifier_kernel<<<1, 128>>>(W1, b1, W2, b2, out);
}

// round 3
// speedup vs baseline: 1.3897x; 1.2086x over previous
#include <cuda_runtime.h>
#include <math.h>
#include <stdint.h>

#define N_NODES 100000
#define N_EDGES 1000000
#define IN_DIM  128
#define HID     64
#define NET     4
#define G_GRAPHS 128
#define LBL     10
#define N_STEPS 5

// ---------------- scratch ----------------
static __device__ float g_h[(size_t)N_NODES * HID];
static __device__ float g_trans[(size_t)N_NODES * NET * HID];
static __device__ float g_a[(size_t)N_NODES * HID];
static __device__ int2  g_eoff[N_EDGES];
static __device__ uint32_t g_wih_t[3 * HID * HID];
static __device__ uint32_t g_whh_t[3 * HID * HID];
static __device__ float g_hg[G_GRAPHS * HID];
static __device__ float g_cnt[G_GRAPHS];

// ---------------- tf32 helpers ----------------
__device__ __forceinline__ uint32_t f2tf(float f) {
    uint32_t r; asm("cvt.rna.tf32.f32 %0, %1;" : "=r"(r) : "f"(f)); return r;
}
__device__ __forceinline__ void mma8(float* c, uint32_t a0, uint32_t a1, uint32_t a2, uint32_t a3,
                                     uint32_t b0, uint32_t b1) {
    asm volatile("mma.sync.aligned.m16n8k8.row.col.f32.tf32.tf32.f32 "
                 "{%0,%1,%2,%3},{%4,%5,%6,%7},{%8,%9},{%0,%1,%2,%3};"
                 : "+f"(c[0]), "+f"(c[1]), "+f"(c[2]), "+f"(c[3])
                 : "r"(a0), "r"(a1), "r"(a2), "r"(a3), "r"(b0), "r"(b1));
}

// ---------------- prep: edge offsets + tf32 weight conversion (once per launch) ----------------
__global__ void prep_kernel(const int* __restrict__ src, const int* __restrict__ dst,
                            const int* __restrict__ et,
                            const float* __restrict__ Wih, const float* __restrict__ Whh) {
    int t = blockIdx.x * blockDim.x + threadIdx.x;
    if (t < 3 * HID * HID) {
        g_wih_t[t] = f2tf(__ldg(Wih + t));
        g_whh_t[t] = f2tf(__ldg(Whh + t));
    }
    if (t < N_EDGES) {
        int s = __ldg(src + t), d = __ldg(dst + t), ty = __ldg(et + t);
        g_eoff[t] = make_int2((s * NET + ty) * HID, d * HID);
    }
}

// ---------------- tf32 GEMM: C[M,NCOLS] = A[M,K] @ W[NCOLS,K]^T + bias ----------------
// BM=128, BN=64 (grid.y covers NCOLS/64), 256 threads = 8 warps (4 row x 2 col),
// each warp computes 32x32 via 2x4 m16n8k8 mma tiles. Fragment-ordered smem.
template<int K, int NCOLS>
__global__ void __launch_bounds__(256) tf32_gemm_bias(
    const float* __restrict__ A, const float* __restrict__ W,
    const float* __restrict__ bias, float* __restrict__ C, int M)
{
    __shared__ uint32_t As[128 * 64];   // 32 KB, frag order: ((mb*8+ks)*32+lane)*4+reg
    __shared__ uint32_t Bs[64 * 64];    // 16 KB, frag order: ((nb*8+ks)*32+lane)*2+reg
    const int tid  = threadIdx.x;
    const int row0 = blockIdx.x * 128;
    const int col0 = blockIdx.y * 64;
    const int warp = tid >> 5, lane = tid & 31;
    const int wm = warp & 3, wn = warp >> 2;

    float acc[2][4][4];
#pragma unroll
    for (int mt = 0; mt < 2; mt++)
#pragma unroll
        for (int nt = 0; nt < 4; nt++)
#pragma unroll
            for (int i = 0; i < 4; i++) acc[mt][nt][i] = 0.f;

    for (int kc = 0; kc < K; kc += 64) {
        // stage A tile 128x64 (fragment-permuted, cvt to tf32)
#pragma unroll
        for (int u = 0; u < 8; u++) {
            int c = tid + u * 256;
            int row = c >> 4, c0 = (c & 15) << 2;
            int gr = row0 + row; if (gr >= M) gr = M - 1;
            float4 v = __ldg((const float4*)(A + (size_t)gr * K + kc + c0));
            int reg  = (((row & 15) >= 8) ? 1 : 0) + (((c0 & 7) >= 4) ? 2 : 0);
            int base = (((row >> 4) * 8 + (c0 >> 3)) * 32 + (row & 7) * 4) * 4 + reg;
            As[base] = f2tf(v.x); As[base + 4] = f2tf(v.y);
            As[base + 8] = f2tf(v.z); As[base + 12] = f2tf(v.w);
        }
        // stage W tile 64x64
#pragma unroll
        for (int u = 0; u < 4; u++) {
            int c = tid + u * 256;
            int n = c >> 4, k0 = (c & 15) << 2;
            float4 v = __ldg((const float4*)(W + (size_t)(col0 + n) * K + kc + k0));
            int reg  = ((k0 & 7) >= 4) ? 1 : 0;
            int base = (((n >> 3) * 8 + (k0 >> 3)) * 32 + (n & 7) * 4) * 2 + reg;
            Bs[base] = f2tf(v.x); Bs[base + 2] = f2tf(v.y);
            Bs[base + 4] = f2tf(v.z); Bs[base + 6] = f2tf(v.w);
        }
        __syncthreads();
#pragma unroll
        for (int ks = 0; ks < 8; ks++) {
            uint4 av[2]; uint2 bv[4];
#pragma unroll
            for (int mt = 0; mt < 2; mt++)
                av[mt] = *(const uint4*)&As[(((wm * 2 + mt) * 8 + ks) * 32 + lane) * 4];
#pragma unroll
            for (int nt = 0; nt < 4; nt++)
                bv[nt] = *(const uint2*)&Bs[(((wn * 4 + nt) * 8 + ks) * 32 + lane) * 2];
#pragma unroll
            for (int mt = 0; mt < 2; mt++)
#pragma unroll
                for (int nt = 0; nt < 4; nt++)
                    mma8(acc[mt][nt], av[mt].x, av[mt].y, av[mt].z, av[mt].w,
                         bv[nt].x, bv[nt].y);
        }
        __syncthreads();
    }

    const int g = lane >> 2, tg = lane & 3;
#pragma unroll
    for (int nt = 0; nt < 4; nt++) {
        int cc = col0 + wn * 32 + nt * 8 + tg * 2;
        float b0 = __ldg(bias + cc), b1 = __ldg(bias + cc + 1);
#pragma unroll
        for (int mt = 0; mt < 2; mt++) {
            int r = row0 + wm * 32 + mt * 16 + g;
            if (r < M)
                *(float2*)(C + (size_t)r * NCOLS + cc) =
                    make_float2(acc[mt][nt][0] + b0, acc[mt][nt][1] + b1);
            if (r + 8 < M)
                *(float2*)(C + (size_t)(r + 8) * NCOLS + cc) =
                    make_float2(acc[mt][nt][2] + b0, acc[mt][nt][3] + b1);
        }
    }
}

// ---------------- fused GRU (tf32 MMA): gates + update + zero g_a for next step ----------------
// BM=64 rows, 128 threads = 4 warps (2 row x 2 col). Sections of W (192 rows): R=0,Z=1,N=2.
// accT trick: accT = h@Whh_n; accT = r*(accT+bhn); accT += a@Wih_n  => n-arg (+bin).
__global__ void __launch_bounds__(128) gru_fused_tf32(
    const float* __restrict__ bih, const float* __restrict__ bhh, int M)
{
    __shared__ uint32_t Aa[64 * 64];  // 16 KB
    __shared__ uint32_t Ah[64 * 64];  // 16 KB
    const int tid  = threadIdx.x;
    const int row0 = blockIdx.x * 64;
    const int warp = tid >> 5, lane = tid & 31;
    const int wm = warp & 1, wn = warp >> 1;
    const int g = lane >> 2, tg = lane & 3;

    // stage a and h tiles (fragment-permuted)
#pragma unroll
    for (int u = 0; u < 8; u++) {
        int c = tid + u * 128;
        int row = c >> 4, c0 = (c & 15) << 2;
        int gr = row0 + row; if (gr >= M) gr = M - 1;
        float4 va = __ldg((const float4*)(g_a + (size_t)gr * HID + c0));
        float4 vh = __ldg((const float4*)(g_h + (size_t)gr * HID + c0));
        int reg  = (((row & 15) >= 8) ? 1 : 0) + (((c0 & 7) >= 4) ? 2 : 0);
        int base = (((row >> 4) * 8 + (c0 >> 3)) * 32 + (row & 7) * 4) * 4 + reg;
        Aa[base] = f2tf(va.x); Aa[base + 4] = f2tf(va.y);
        Aa[base + 8] = f2tf(va.z); Aa[base + 12] = f2tf(va.w);
        Ah[base] = f2tf(vh.x); Ah[base + 4] = f2tf(vh.y);
        Ah[base + 8] = f2tf(vh.z); Ah[base + 12] = f2tf(vh.w);
    }
    __syncthreads();

    float accR[2][4][4], accZ[2][4][4], accT[2][4][4];
#pragma unroll
    for (int mt = 0; mt < 2; mt++)
#pragma unroll
        for (int nt = 0; nt < 4; nt++)
#pragma unroll
            for (int i = 0; i < 4; i++) { accR[mt][nt][i] = 0.f; accZ[mt][nt][i] = 0.f; accT[mt][nt][i] = 0.f; }

    // phase 1: R and Z sections, both passes (a@Wih, h@Whh)
#pragma unroll
    for (int p = 0; p < 2; p++) {
        const uint32_t* Asm = p ? Ah : Aa;
        const uint32_t* Wt  = p ? g_whh_t : g_wih_t;
#pragma unroll
        for (int sec = 0; sec < 2; sec++) {
            const uint32_t* wb = Wt + (size_t)(sec * 64 + wn * 32 + g) * HID + tg;
#pragma unroll
            for (int ks = 0; ks < 8; ks++) {
                uint4 av[2];
#pragma unroll
                for (int mt = 0; mt < 2; mt++)
                    av[mt] = *(const uint4*)&Asm[(((wm * 2 + mt) * 8 + ks) * 32 + lane) * 4];
#pragma unroll
                for (int nt = 0; nt < 4; nt++) {
                    uint32_t b0 = __ldg(wb + nt * 8 * HID + ks * 8);
                    uint32_t b1 = __ldg(wb + nt * 8 * HID + ks * 8 + 4);
#pragma unroll
                    for (int mt = 0; mt < 2; mt++) {
                        float* acc = sec ? accZ[mt][nt] : accR[mt][nt];
                        mma8(acc, av[mt].x, av[mt].y, av[mt].z, av[mt].w, b0, b1);
                    }
                }
            }
        }
    }

    // phase 2a: accT = h @ Whh_n
    {
        const uint32_t* wb = g_whh_t + (size_t)(128 + wn * 32 + g) * HID + tg;
#pragma unroll
        for (int ks = 0; ks < 8; ks++) {
            uint4 av[2];
#pragma unroll
            for (int mt = 0; mt < 2; mt++)
                av[mt] = *(const uint4*)&Ah[(((wm * 2 + mt) * 8 + ks) * 32 + lane) * 4];
#pragma unroll
            for (int nt = 0; nt < 4; nt++) {
                uint32_t b0 = __ldg(wb + nt * 8 * HID + ks * 8);
                uint32_t b1 = __ldg(wb + nt * 8 * HID + ks * 8 + 4);
#pragma unroll
                for (int mt = 0; mt < 2; mt++)
                    mma8(accT[mt][nt], av[mt].x, av[mt].y, av[mt].z, av[mt].w, b0, b1);
            }
        }
    }

    // r = sigmoid(accR + br); accT = r * (accT + bhn)
#pragma unroll
    for (int nt = 0; nt < 4; nt++) {
        int cc = wn * 32 + nt * 8 + tg * 2;
        float br0 = __ldg(bih + cc) + __ldg(bhh + cc);
        float br1 = __ldg(bih + cc + 1) + __ldg(bhh + cc + 1);
        float bn0 = __ldg(bhh + 128 + cc);
        float bn1 = __ldg(bhh + 128 + cc + 1);
#pragma unroll
        for (int mt = 0; mt < 2; mt++)
#pragma unroll
            for (int i = 0; i < 4; i++) {
                float brv = (i & 1) ? br1 : br0;
                float bnv = (i & 1) ? bn1 : bn0;
                float r = 1.f / (1.f + __expf(-(accR[mt][nt][i] + brv)));
                accT[mt][nt][i] = r * (accT[mt][nt][i] + bnv);
            }
    }

    // phase 2b: accT += a @ Wih_n
    {
        const uint32_t* wb = g_wih_t + (size_t)(128 + wn * 32 + g) * HID + tg;
#pragma unroll
        for (int ks = 0; ks < 8; ks++) {
            uint4 av[2];
#pragma unroll
            for (int mt = 0; mt < 2; mt++)
                av[mt] = *(const uint4*)&Aa[(((wm * 2 + mt) * 8 + ks) * 32 + lane) * 4];
#pragma unroll
            for (int nt = 0; nt < 4; nt++) {
                uint32_t b0 = __ldg(wb + nt * 8 * HID + ks * 8);
                uint32_t b1 = __ldg(wb + nt * 8 * HID + ks * 8 + 4);
#pragma unroll
                for (int mt = 0; mt < 2; mt++)
                    mma8(accT[mt][nt], av[mt].x, av[mt].y, av[mt].z, av[mt].w, b0, b1);
            }
        }
    }

    // epilogue: z, n, h update; zero g_a for the next step's scatter
#pragma unroll
    for (int nt = 0; nt < 4; nt++) {
        int cc = wn * 32 + nt * 8 + tg * 2;
        float bz0 = __ldg(bih + 64 + cc) + __ldg(bhh + 64 + cc);
        float bz1 = __ldg(bih + 64 + cc + 1) + __ldg(bhh + 64 + cc + 1);
        float bi0 = __ldg(bih + 128 + cc);
        float bi1 = __ldg(bih + 128 + cc + 1);
#pragma unroll
        for (int mt = 0; mt < 2; mt++) {
#pragma unroll
            for (int half = 0; half < 2; half++) {
                int r = row0 + wm * 32 + mt * 16 + g + half * 8;
                if (r < M) {
                    float* hp = g_h + (size_t)r * HID + cc;
                    float2 ho = *(const float2*)hp;
                    int i0 = half * 2;
                    float z0 = 1.f / (1.f + __expf(-(accZ[mt][nt][i0] + bz0)));
                    float z1 = 1.f / (1.f + __expf(-(accZ[mt][nt][i0 + 1] + bz1)));
                    float n0 = tanhf(accT[mt][nt][i0] + bi0);
                    float n1 = tanhf(accT[mt][nt][i0 + 1] + bi1);
                    *(float2*)hp = make_float2((1.f - z0) * n0 + z0 * ho.x,
                                               (1.f - z1) * n1 + z1 * ho.y);
                    *(float2*)(g_a + (size_t)r * HID + cc) = make_float2(0.f, 0.f);
                }
            }
        }
    }
}

// ---------------- zero helpers ----------------
__global__ void zero_a() {
    size_t t = (size_t)blockIdx.x * blockDim.x + threadIdx.x;
    size_t n4 = (size_t)N_NODES * HID / 4;
    if (t < n4) ((float4*)g_a)[t] = make_float4(0.f, 0.f, 0.f, 0.f);
}
__global__ void zero_pool() {
    int t = threadIdx.x;
    for (int i = t; i < G_GRAPHS * HID; i += blockDim.x) g_hg[i] = 0.f;
    if (t < G_GRAPHS) g_cnt[t] = 0.f;
}

// ---------------- edge scatter: a[dstoff] += trans[srcoff] ----------------
__global__ void edge_scatter() {
    int t = blockIdx.x * blockDim.x + threadIdx.x;
    int e = t >> 4;
    if (e >= N_EDGES) return;
    int lane = threadIdx.x & 31;
    int so = 0, dofs = 0;
    if ((lane & 15) == 0) { int2 o = __ldg(&g_eoff[e]); so = o.x; dofs = o.y; }
    so   = __shfl_sync(0xffffffffu, so,   lane & 16);
    dofs = __shfl_sync(0xffffffffu, dofs, lane & 16);
    int q = (t & 15) << 2;
    float4 v = __ldg((const float4*)&g_trans[(size_t)so + q]);
    float* out = &g_a[(size_t)dofs + q];
    asm volatile("red.global.add.v4.f32 [%0], {%1,%2,%3,%4};"
                 :: "l"(out), "f"(v.x), "f"(v.y), "f"(v.z), "f"(v.w) : "memory");
}

// ---------------- per-graph mean pool ----------------
__global__ void pool_kernel(const int* __restrict__ n2g) {
    constexpr int CHUNK = 256;
    int j = threadIdx.x;
    int start = blockIdx.x * CHUNK;
    int end   = min(start + CHUNK, N_NODES);
    if (start >= end) return;
    float sum = 0.f, c = 0.f;
    int g = __ldg(n2g + start);
    for (int n = start; n < end; n++) {
        int gn = __ldg(n2g + n);
        if (gn != g) {
            atomicAdd(&g_hg[g * HID + j], sum);
            if (j == 0) atomicAdd(&g_cnt[g], c);
            sum = 0.f; c = 0.f; g = gn;
        }
        sum += g_h[(size_t)n * HID + j];
        c += 1.f;
    }
    atomicAdd(&g_hg[g * HID + j], sum);
    if (j == 0) atomicAdd(&g_cnt[g], c);
}

// ---------------- classifier ----------------
__global__ void classifier_kernel(const float* __restrict__ W1, const float* __restrict__ b1,
                                  const float* __restrict__ W2, const float* __restrict__ b2,
                                  float* __restrict__ out)
{
    __shared__ float sW1[32 * 64];
    __shared__ float sW2[10 * 32];
    __shared__ float sHG[G_GRAPHS][HID + 1];
    int t = threadIdx.x;
    for (int i = t; i < 32 * 64; i += 128) sW1[i] = W1[i];
    for (int i = t; i < 10 * 32; i += 128) sW2[i] = W2[i];
    for (int i = t; i < G_GRAPHS * HID; i += 128) {
        int g = i >> 6;
        sHG[g][i & 63] = g_hg[i] / fmaxf(g_cnt[g], 1.f);
    }
    __syncthreads();
    int g = t;
    float mid[32];
#pragma unroll
    for (int m = 0; m < 32; m++) {
        float s = b1[m];
#pragma unroll
        for (int k = 0; k < 64; k++) s += sHG[g][k] * sW1[m * 64 + k];
        mid[m] = fmaxf(s, 0.f);
    }
#pragma unroll
    for (int l = 0; l < LBL; l++) {
        float s = b2[l];
#pragma unroll
        for (int k = 0; k < 32; k++) s += mid[k] * sW2[l * 32 + k];
        out[g * LBL + l] = s;
    }
}

// ---------------- launch ----------------
extern "C" void kernel_launch(void* const* d_in, const int* in_sizes, int n_in,
                              void* d_out, int out_size)
{
    const float* x    = (const float*)d_in[0];
    const int*   src  = (const int*)d_in[1];
    const int*   dst  = (const int*)d_in[2];
    const int*   et   = (const int*)d_in[3];
    const int*   n2g  = (const int*)d_in[4];
    const float* W_in = (const float*)d_in[5];
    const float* b_in = (const float*)d_in[6];
    const float* We   = (const float*)d_in[7];
    const float* be   = (const float*)d_in[8];
    const float* W_ih = (const float*)d_in[9];
    const float* b_ih = (const float*)d_in[10];
    const float* W_hh = (const float*)d_in[11];
    const float* b_hh = (const float*)d_in[12];
    const float* W1   = (const float*)d_in[13];
    const float* b1   = (const float*)d_in[14];
    const float* W2   = (const float*)d_in[15];
    const float* b2   = (const float*)d_in[16];
    float* out = (float*)d_out;

    void *p;
    cudaGetSymbolAddress(&p, g_h);     float* ph  = (float*)p;
    cudaGetSymbolAddress(&p, g_trans); float* ptr = (float*)p;

    const int M = N_NODES;
    const int gx = (M + 127) / 128;

    prep_kernel<<<(N_EDGES + 255) / 256, 256>>>(src, dst, et, W_ih, W_hh);
    zero_a<<<((N_NODES * HID / 4) + 255) / 256, 256>>>();

    // h = x @ W_in^T + b_in   (K=128, 64 out cols)
    tf32_gemm_bias<IN_DIM, HID><<<dim3(gx, 1), 256>>>(x, W_in, b_in, ph, M);

    for (int s = 0; s < N_STEPS; s++) {
        tf32_gemm_bias<HID, NET * HID><<<dim3(gx, NET), 256>>>(ph, We, be, ptr, M);
        edge_scatter<<<(int)(((long long)N_EDGES * 16 + 255) / 256), 256>>>();
        gru_fused_tf32<<<(M + 63) / 64, 128>>>(b_ih, b_hh, M);  // also zeroes g_a
    }

    zero_pool<<<1, 256>>>();
    pool_kernel<<<(M + 255) / 256, 64>>>(n2g);
    classifier_kernel<<<1, 128>>>(W1, b1, W2, b2, out);
}